// round 6
// baseline (speedup 1.0000x reference)
#include <cuda_runtime.h>

// x: [8, 64, 64, 64, 64] fp32. Per (b,c) slice of 64^3:
//   s = sum over 2x2x2 windows of (max(window) + mean(window))
//   pooled[b,c] = s^2 ;  out[b,c] = pooled / max(||pooled[b,:]||_2, 1e-12)
//
// 1024 blocks = 512 slices x 2 half-slices (512 KB contiguous each).
// __launch_bounds__(256,7) pins regs <=36 so all 1024 blocks stay resident
// in ONE wave (65536 regs/SM / 7 blk / 256 thr = 36), while unroll-4 lets
// ptxas batch more LDG.128s in flight within that budget.

#define CH 2
#define NBC 512
#define NBLK (NBC * CH)   // 1024

__device__ float g_partial[NBLK];
__device__ unsigned int g_counter = 0;

__global__ __launch_bounds__(256, 7) void fused_pool_kernel(const float* __restrict__ x,
                                                            float* __restrict__ out) {
    const int bc    = blockIdx.x >> 1;
    const int half  = blockIdx.x & 1;

    const int tid = threadIdx.x;       // 256 threads
    const int tx  = tid & 15;          // d-group: d = 4*tx..4*tx+3 (two d2 windows)
    const int g   = tid >> 4;          // 0..15: w2 start; strides w2 by 16

    // start: h2 = half*16, w2 = g, d = 4*tx
    const float* r0 = x + (size_t)bc * (64 * 64 * 64)
                        + ((size_t)(half * 32) * 4096) + (2 * g * 64) + (tx << 2);

    float acc = 0.0f;

    #pragma unroll 4
    for (int h2i = 0; h2i < 16; h2i++) {          // 16 h2 rows in this half
        const float* r = r0;
        #pragma unroll
        for (int w2i = 0; w2i < 2; w2i++) {       // w2 = g, g+16
            const float4 a = *(const float4*)(r);                 // (2h2,   2w2  )
            const float4 b = *(const float4*)(r + 64);            // (2h2,   2w2+1)
            const float4 c = *(const float4*)(r + 4096);          // (2h2+1, 2w2  )
            const float4 d = *(const float4*)(r + 4096 + 64);     // (2h2+1, 2w2+1)

            float m0 = fmaxf(fmaxf(fmaxf(a.x, a.y), fmaxf(b.x, b.y)),
                             fmaxf(fmaxf(c.x, c.y), fmaxf(d.x, d.y)));
            float m1 = fmaxf(fmaxf(fmaxf(a.z, a.w), fmaxf(b.z, b.w)),
                             fmaxf(fmaxf(c.z, c.w), fmaxf(d.z, d.w)));

            float sum = (a.x + a.y + a.z + a.w) + (b.x + b.y + b.z + b.w)
                      + (c.x + c.y + c.z + c.w) + (d.x + d.y + d.z + d.w);

            acc += m0 + m1 + sum * 0.125f;
            r += 2 * 16 * 64;                     // w2 += 16
        }
        r0 += 2 * 4096;                           // h2 += 1
    }

    // block reduce: warp shuffle then smem across 8 warps
    __shared__ float swarp[8];
    __shared__ int s_islast;
    #pragma unroll
    for (int off = 16; off > 0; off >>= 1)
        acc += __shfl_xor_sync(0xFFFFFFFFu, acc, off);
    if ((tid & 31) == 0) swarp[tid >> 5] = acc;
    __syncthreads();

    if (tid == 0) {
        float t = swarp[0] + swarp[1] + swarp[2] + swarp[3]
                + swarp[4] + swarp[5] + swarp[6] + swarp[7];
        g_partial[blockIdx.x] = t;
        __threadfence();                          // publish before ticket
        unsigned int old = atomicAdd(&g_counter, 1u);
        s_islast = (old == (unsigned int)(gridDim.x - 1));
    }
    __syncthreads();
    if (!s_islast) return;

    // ---- last block: finalize (all 1024 partials visible) ----
    __threadfence();
    __shared__ float s_norm[8];

    const int w = tid >> 5;            // warp 0..7 -> batch b
    const int l = tid & 31;            // lane -> channels l and l+32

    const int i0 = (w * 64 + l) * CH;
    const int i1 = (w * 64 + l + 32) * CH;
    const float s0 = g_partial[i0] + g_partial[i0 + 1];
    const float s1 = g_partial[i1] + g_partial[i1 + 1];
    const float p0 = s0 * s0;
    const float p1 = s1 * s1;

    float q = p0 * p0 + p1 * p1;
    #pragma unroll
    for (int off = 16; off > 0; off >>= 1)
        q += __shfl_xor_sync(0xFFFFFFFFu, q, off);

    if (l == 0) s_norm[w] = fmaxf(sqrtf(q), 1e-12f);
    __syncthreads();

    const float inv = 1.0f / s_norm[w];
    out[w * 64 + l]      = p0 * inv;
    out[w * 64 + l + 32] = p1 * inv;

    if (tid == 0) g_counter = 0;       // reset for next graph replay
}

extern "C" void kernel_launch(void* const* d_in, const int* in_sizes, int n_in,
                              void* d_out, int out_size) {
    const float* x = (const float*)d_in[0];
    float* out = (float*)d_out;
    fused_pool_kernel<<<NBLK, 256>>>(x, out);
}

// round 7
// speedup vs baseline: 1.0139x; 1.0139x over previous
#include <cuda_runtime.h>

// x: [8, 64, 64, 64, 64] fp32. Per (b,c) slice of 64^3:
//   s = sum over 2x2x2 windows of (max(window) + mean(window))
//   pooled[b,c] = s^2 ;  out[b,c] = pooled / max(||pooled[b,:]||_2, 1e-12)
//
// 2048 blocks x 128 threads = 512 slices x 4 quarter-slices (256 KB each).
// 32 regs x 128 thr -> 16 blocks/SM residency cap, so ALL 2048 blocks fit in
// ONE wave (need 14/SM): per-SM imbalance is a single 256 KB block (~2%),
// and 124/148 SMs still stream during the tail. Fused last-block finalize.

#define CH 4
#define NBC 512
#define NBLK (NBC * CH)   // 2048

__device__ float g_partial[NBLK];
__device__ unsigned int g_counter = 0;

__global__ __launch_bounds__(128, 16) void fused_pool_kernel(const float* __restrict__ x,
                                                             float* __restrict__ out) {
    const int bc = blockIdx.x >> 2;
    const int q  = blockIdx.x & 3;     // quarter: h2 in [q*8, q*8+8)

    const int tid = threadIdx.x;       // 128 threads
    const int tx  = tid & 15;          // d-group: d = 4*tx..4*tx+3 (two d2 windows)
    const int g   = tid >> 4;          // 0..7: w2 start; strides w2 by 8

    // start: h2 = q*8, w2 = g, d = 4*tx
    const float* r0 = x + (size_t)bc * (64 * 64 * 64)
                        + ((size_t)(q * 16) * 4096) + (2 * g * 64) + (tx << 2);

    float acc = 0.0f;

    for (int h2i = 0; h2i < 8; h2i++) {           // 8 h2 rows in this quarter
        const float* r = r0;
        #pragma unroll
        for (int w2i = 0; w2i < 4; w2i++) {       // w2 = g, g+8, g+16, g+24
            const float4 a = *(const float4*)(r);                 // (2h2,   2w2  )
            const float4 b = *(const float4*)(r + 64);            // (2h2,   2w2+1)
            const float4 c = *(const float4*)(r + 4096);          // (2h2+1, 2w2  )
            const float4 d = *(const float4*)(r + 4096 + 64);     // (2h2+1, 2w2+1)

            float m0 = fmaxf(fmaxf(fmaxf(a.x, a.y), fmaxf(b.x, b.y)),
                             fmaxf(fmaxf(c.x, c.y), fmaxf(d.x, d.y)));
            float m1 = fmaxf(fmaxf(fmaxf(a.z, a.w), fmaxf(b.z, b.w)),
                             fmaxf(fmaxf(c.z, c.w), fmaxf(d.z, d.w)));

            float sum = (a.x + a.y + a.z + a.w) + (b.x + b.y + b.z + b.w)
                      + (c.x + c.y + c.z + c.w) + (d.x + d.y + d.z + d.w);

            acc += m0 + m1 + sum * 0.125f;
            r += 2 * 8 * 64;                      // w2 += 8
        }
        r0 += 2 * 4096;                           // h2 += 1
    }

    // block reduce: warp shuffle then smem across 4 warps
    __shared__ float swarp[4];
    __shared__ int s_islast;
    #pragma unroll
    for (int off = 16; off > 0; off >>= 1)
        acc += __shfl_xor_sync(0xFFFFFFFFu, acc, off);
    if ((tid & 31) == 0) swarp[tid >> 5] = acc;
    __syncthreads();

    if (tid == 0) {
        float t = swarp[0] + swarp[1] + swarp[2] + swarp[3];
        g_partial[blockIdx.x] = t;
        __threadfence();                          // publish before ticket
        unsigned int old = atomicAdd(&g_counter, 1u);
        s_islast = (old == (unsigned int)(gridDim.x - 1));
    }
    __syncthreads();
    if (!s_islast) return;

    // ---- last block: finalize (all 2048 partials visible) ----
    __threadfence();
    __shared__ float s_norm[8];

    // 128 threads: warp w (0..3) handles batches 2w and 2w+1? Simpler:
    // each of 128 threads covers 4 channels of one (b,c) row-major chunk.
    // Layout: thread t -> (b = t >> 4, c4 = (t & 15)*4): 8 batches x 16 groups.
    const int b  = tid >> 4;           // 0..7
    const int c4 = (tid & 15) << 2;    // 0,4,...,60

    float p[4], qsum = 0.0f;
    #pragma unroll
    for (int k = 0; k < 4; k++) {
        const int idx = ((b << 6) + c4 + k) * CH;
        const float s = g_partial[idx] + g_partial[idx + 1]
                      + g_partial[idx + 2] + g_partial[idx + 3];
        p[k] = s * s;
        qsum += p[k] * p[k];
    }

    // reduce qsum over the 16 threads of the same batch (tx groups of 16
    // within a warp: threads [b*16, b*16+16) are contiguous -> two batches
    // per warp; use shfl over 16 lanes).
    #pragma unroll
    for (int off = 8; off > 0; off >>= 1)
        qsum += __shfl_xor_sync(0xFFFFFFFFu, qsum, off);

    if ((tid & 15) == 0) s_norm[b] = fmaxf(sqrtf(qsum), 1e-12f);
    __syncthreads();

    const float inv = 1.0f / s_norm[b];
    #pragma unroll
    for (int k = 0; k < 4; k++)
        out[(b << 6) + c4 + k] = p[k] * inv;

    if (tid == 0) g_counter = 0;       // reset for next graph replay
}

extern "C" void kernel_launch(void* const* d_in, const int* in_sizes, int n_in,
                              void* d_out, int out_size) {
    const float* x = (const float*)d_in[0];
    float* out = (float*)d_out;
    fused_pool_kernel<<<NBLK, 128>>>(x, out);
}